// round 14
// baseline (speedup 1.0000x reference)
#include <cuda_runtime.h>

#define NN 100000
#define EE 640000
#define GG 64
#define BN_EPS 1e-5f
#define SLOPE 0.01f
#define NB_SCAN 98   // ceil(100000/1024)

// ---------------- scratch (static device buffers) ---------------------------
__device__ int   g_deg[NN];
__device__ float g_dinv[NN];
__device__ int   g_cnt[NN];
__device__ int   g_rowptr[NN + 1];
__device__ int   g_cursor[NN];
__device__ int   g_bsums[128];
__device__ int   g_boffs[130];
__device__ int   g_csr_src[EE];
__device__ float g_csr_w[EE];

__device__ __align__(16) float g_ZC[NN * 192];   // packed [Z0|Z1|Z2] per layer
__device__ __align__(16) float g_S [NN * 64];
__device__ __align__(16) float g_H1[NN * 64];
__device__ __align__(16) float g_H2[NN * 32];
__device__ __align__(16) float g_H3[NN * 16];

__device__ __align__(16) float g_Wc1[128 * 192];  // [f][ Wd | W1 | W2 ]
__device__ __align__(16) float g_Wc2[64 * 96];
__device__ __align__(16) float g_Wc3[32 * 48];
__device__ __align__(16) float g_sc1[64], g_sh1[64];
__device__ __align__(16) float g_sc2[32], g_sh2[32];
__device__ __align__(16) float g_sc3[16], g_sh3[16];

__device__ float g_pooled[GG * 16];
__device__ int   g_pcnt[GG];

// ---------------- f32x2 packed helpers -------------------------------------
__device__ __forceinline__ unsigned long long ffma2(unsigned long long a,
                                                    unsigned long long b,
                                                    unsigned long long c) {
    unsigned long long d;
    asm("fma.rn.f32x2 %0, %1, %2, %3;" : "=l"(d) : "l"(a), "l"(b), "l"(c));
    return d;
}
__device__ __forceinline__ unsigned long long dup2(float h) {
    unsigned long long r;
    unsigned hi = __float_as_uint(h);
    asm("mov.b64 %0, {%1, %1};" : "=l"(r) : "r"(hi));
    return r;
}
__device__ __forceinline__ void unpack2(unsigned long long v, float& lo, float& hi) {
    unsigned a, b;
    asm("mov.b64 {%0, %1}, %2;" : "=r"(a), "=r"(b) : "l"(v));
    lo = __uint_as_float(a);
    hi = __uint_as_float(b);
}

// ---------------- init ------------------------------------------------------
__global__ void k_zero() {
    int i = blockIdx.x * blockDim.x + threadIdx.x;
    if (i < NN) { g_deg[i] = 0; g_cnt[i] = 0; g_cursor[i] = 0; }
    if (i < GG * 16) g_pooled[i] = 0.f;
    if (i < GG) g_pcnt[i] = 0;
}

__global__ void k_count(const int* __restrict__ ei) {
    int e = blockIdx.x * blockDim.x + threadIdx.x;
    if (e >= EE) return;
    int s = ei[e], d = ei[EE + e];
    if (s != d) {
        atomicAdd(&g_deg[s], 1);
        atomicAdd(&g_cnt[d], 1);
    }
}

// ---------------- exclusive scan of g_cnt -> g_rowptr (+ dinv fused) -------
__global__ void k_scan1() {
    __shared__ int sm[1024];
    int t = threadIdx.x;
    int i = blockIdx.x * 1024 + t;
    int v = (i < NN) ? g_cnt[i] : 0;
    if (i < NN) {   // fused dinv (g_deg final after k_count)
        int dg = g_deg[i];
        g_dinv[i] = (dg > 0) ? rsqrtf((float)dg) : 0.f;
    }
    sm[t] = v;
    __syncthreads();
    for (int off = 1; off < 1024; off <<= 1) {
        int add = (t >= off) ? sm[t - off] : 0;
        __syncthreads();
        sm[t] += add;
        __syncthreads();
    }
    if (i < NN) g_rowptr[i] = sm[t] - v;
    if (t == 1023) g_bsums[blockIdx.x] = sm[1023];
}

__global__ void k_scan2(int nb) {
    __shared__ int sm[128];
    int t = threadIdx.x;
    int v = (t < nb) ? g_bsums[t] : 0;
    sm[t] = v;
    __syncthreads();
    for (int off = 1; off < 128; off <<= 1) {
        int add = (t >= off) ? sm[t - off] : 0;
        __syncthreads();
        sm[t] += add;
        __syncthreads();
    }
    if (t < nb) g_boffs[t] = sm[t] - v;
    if (t == nb - 1) g_boffs[nb] = sm[t];
}

__global__ void k_scan3(int nb) {
    int i = blockIdx.x * blockDim.x + threadIdx.x;
    if (i < NN) g_rowptr[i] += g_boffs[i >> 10];
    if (i == 0) g_rowptr[NN] = g_boffs[nb];
}

__global__ void k_fill(const int* __restrict__ ei) {
    int e = blockIdx.x * blockDim.x + threadIdx.x;
    if (e >= EE) return;
    int s = ei[e], d = ei[EE + e];
    if (s == d) return;
    float wv = -g_dinv[s] * g_dinv[d];
    int pos = g_rowptr[d] + atomicAdd(&g_cursor[d], 1);
    g_csr_src[pos] = s;
    g_csr_w[pos]   = wv;
}

// ---------------- prep: concatenated weights + BN affine fold ---------------
__global__ void k_prep(const float* __restrict__ W1, const float* __restrict__ W2,
                       const float* __restrict__ W3,
                       const float* __restrict__ b1, const float* __restrict__ gg1,
                       const float* __restrict__ be1, const float* __restrict__ m1,
                       const float* __restrict__ v1,
                       const float* __restrict__ b2, const float* __restrict__ gg2,
                       const float* __restrict__ be2, const float* __restrict__ m2,
                       const float* __restrict__ v2,
                       const float* __restrict__ b3, const float* __restrict__ gg3,
                       const float* __restrict__ be3, const float* __restrict__ m3,
                       const float* __restrict__ v3) {
    int i = blockIdx.x * blockDim.x + threadIdx.x;
    if (i < 24576) {                        // 128 x 192
        int f = i / 192, c = i % 192;
        int sec = c / 64, cc = c - sec * 64;
        int base = f * 64 + cc;
        float v = (sec == 0) ? (W1[base] - W1[16384 + base]) : W1[sec * 8192 + base];
        g_Wc1[i] = v;
    } else if (i < 24576 + 6144) {          // 64 x 96
        int j = i - 24576;
        int f = j / 96, c = j % 96;
        int sec = c / 32, cc = c - sec * 32;
        int base = f * 32 + cc;
        float v = (sec == 0) ? (W2[base] - W2[4096 + base]) : W2[sec * 2048 + base];
        g_Wc2[j] = v;
    } else if (i < 24576 + 6144 + 1536) {   // 32 x 48
        int j = i - 24576 - 6144;
        int f = j / 48, c = j % 48;
        int sec = c / 16, cc = c - sec * 16;
        int base = f * 16 + cc;
        float v = (sec == 0) ? (W3[base] - W3[1024 + base]) : W3[sec * 512 + base];
        g_Wc3[j] = v;
    } else if (i < 24576 + 6144 + 1536 + 64) {
        int o = i - (24576 + 6144 + 1536);
        float s = gg1[o] * rsqrtf(v1[o] + BN_EPS);
        g_sc1[o] = s;
        g_sh1[o] = be1[o] + (b1[o] - m1[o]) * s;
    } else if (i < 24576 + 6144 + 1536 + 64 + 32) {
        int o = i - (24576 + 6144 + 1536 + 64);
        float s = gg2[o] * rsqrtf(v2[o] + BN_EPS);
        g_sc2[o] = s;
        g_sh2[o] = be2[o] + (b2[o] - m2[o]) * s;
    } else if (i < 24576 + 6144 + 1536 + 64 + 32 + 16) {
        int o = i - (24576 + 6144 + 1536 + 64 + 32);
        float s = gg3[o] * rsqrtf(v3[o] + BN_EPS);
        g_sc3[o] = s;
        g_sh3[o] = be3[o] + (b3[o] - m3[o]) * s;
    }
}

// ---------------- persistent-W pipelined GEMM (unchanged from R13) ----------
template <int Fin, int Fout, int CT, int BR>
__global__ void __launch_bounds__(256)
k_gemm(const float* __restrict__ X, const float* __restrict__ Wc,
       float* __restrict__ ZC) {
    constexpr int N3     = 3 * Fout;
    constexpr int TC     = 6;                 // N3 / CT
    constexpr int RT     = 256 / CT;
    constexpr int TR     = BR / RT;           // 8 for all layers
    constexpr int PAIRS  = TR / 2;            // 4
    constexpr int KS     = Fin / 16;          // k slabs (even)
    constexpr int PER    = (BR * 4) / 256;    // staged float4s per thread
    constexpr int NCHK   = (NN + BR - 1) / BR;

    extern __shared__ float smem[];
    float* Ws = smem;                         // [Fin][N3]
    float* Xs = smem + Fin * N3;              // [2][16][BR]

    int tid = threadIdx.x;
    int ct = tid % CT, rt = tid / CT;
    int tr0 = rt * TR;
    int sr  = tid % BR;                       // staging row
    int kq0 = tid / BR;                       // staging k-quad base

    // load W once
    for (int i = tid; i < Fin * N3 / 4; i += 256)
        *reinterpret_cast<float4*>(Ws + i * 4) =
            *reinterpret_cast<const float4*>(Wc + i * 4);
    __syncthreads();

    for (int chunk = blockIdx.x; chunk < NCHK; chunk += gridDim.x) {
        int row0 = chunk * BR;
        const float* xbase = X + (size_t)min(row0 + sr, NN - 1) * Fin;

        unsigned long long acc[PAIRS][TC];
#pragma unroll
        for (int p = 0; p < PAIRS; p++)
#pragma unroll
            for (int c = 0; c < TC; c++) acc[p][c] = 0ull;

        float4 xreg[PER];
#pragma unroll
        for (int q = 0; q < PER; q++)
            xreg[q] = *reinterpret_cast<const float4*>(
                xbase + (kq0 + q * (256 / BR)) * 4);

#pragma unroll
        for (int ki = 0; ki < KS; ki++) {
            float* Xb = Xs + (ki & 1) * (16 * BR);
#pragma unroll
            for (int q = 0; q < PER; q++) {
                int kq = kq0 + q * (256 / BR);
                Xb[(kq * 4 + 0) * BR + sr] = xreg[q].x;
                Xb[(kq * 4 + 1) * BR + sr] = xreg[q].y;
                Xb[(kq * 4 + 2) * BR + sr] = xreg[q].z;
                Xb[(kq * 4 + 3) * BR + sr] = xreg[q].w;
            }
            if (ki + 1 < KS) {   // prefetch next slab (hidden under compute)
#pragma unroll
                for (int q = 0; q < PER; q++)
                    xreg[q] = *reinterpret_cast<const float4*>(
                        xbase + (ki + 1) * 16 + (kq0 + q * (256 / BR)) * 4);
            }
            __syncthreads();     // single barrier per slab

            const float* Wk = Ws + ki * 16 * N3 + ct;

            // ---- software-pipelined kk loop (double reg buffer) ----
            float wv[2][TC];
            unsigned long long xp[2][PAIRS];
#pragma unroll
            for (int c = 0; c < TC; c++) wv[0][c] = Wk[c * CT];
            {
                const float* xrow = Xb + tr0;
                ulonglong2 a = *reinterpret_cast<const ulonglong2*>(xrow);
                ulonglong2 b = *reinterpret_cast<const ulonglong2*>(xrow + 4);
                xp[0][0] = a.x; xp[0][1] = a.y; xp[0][2] = b.x; xp[0][3] = b.y;
            }
#pragma unroll
            for (int kk = 0; kk < 16; kk++) {
                int cur = kk & 1, nxt = cur ^ 1;
                if (kk + 1 < 16) {
#pragma unroll
                    for (int c = 0; c < TC; c++)
                        wv[nxt][c] = Wk[(kk + 1) * N3 + c * CT];
                    const float* xrow = Xb + (kk + 1) * BR + tr0;
                    ulonglong2 a = *reinterpret_cast<const ulonglong2*>(xrow);
                    ulonglong2 b = *reinterpret_cast<const ulonglong2*>(xrow + 4);
                    xp[nxt][0] = a.x; xp[nxt][1] = a.y;
                    xp[nxt][2] = b.x; xp[nxt][3] = b.y;
                }
#pragma unroll
                for (int c = 0; c < TC; c++) {
                    unsigned long long wd = dup2(wv[cur][c]);
#pragma unroll
                    for (int p = 0; p < PAIRS; p++)
                        acc[p][c] = ffma2(xp[cur][p], wd, acc[p][c]);
                }
            }
        }

#pragma unroll
        for (int p = 0; p < PAIRS; p++) {
            int row = row0 + tr0 + 2 * p;
            float lo[TC], hi[TC];
#pragma unroll
            for (int c = 0; c < TC; c++) unpack2(acc[p][c], lo[c], hi[c]);
            if (row < NN) {
#pragma unroll
                for (int c = 0; c < TC; c++)
                    ZC[(size_t)row * N3 + c * CT + ct] = lo[c];
            }
            if (row + 1 < NN) {
#pragma unroll
                for (int c = 0; c < TC; c++)
                    ZC[(size_t)(row + 1) * N3 + c * CT + ct] = hi[c];
            }
        }
    }
}

// ---------------- props: VEC=8 (2x float4 per lane), more edges in flight ---
// Each lane covers 8 features; LPN = F/8 lanes per edge, EPW = 32/LPN edge
// subgroups, unroll-2 on top -> 8-32 edges in flight per warp.  Per-edge
// gather is still one 256B-contiguous row segment split across the subgroup.

template <int F>
struct PCfg { static constexpr int LPN = F / 8; };   // 8 / 4 / 2

template <int F>
__device__ __forceinline__ void prop_gather8(const float* __restrict__ Xg, int xs,
                                             int beg, int end, int sub, int fl,
                                             float4& rl, float4& rh) {
    constexpr int EPW = 32 / PCfg<F>::LPN;
    float4 a0l = make_float4(0.f, 0.f, 0.f, 0.f), a0h = a0l;
    float4 a1l = a0l, a1h = a0l;
    int idx = beg + sub;
    for (; idx + EPW < end; idx += 2 * EPW) {
        int s0 = g_csr_src[idx],  s1 = g_csr_src[idx + EPW];
        float w0 = g_csr_w[idx],  w1 = g_csr_w[idx + EPW];
        const float* p0 = Xg + (size_t)s0 * xs + fl * 8;
        const float* p1 = Xg + (size_t)s1 * xs + fl * 8;
        float4 x0l = *reinterpret_cast<const float4*>(p0);
        float4 x0h = *reinterpret_cast<const float4*>(p0 + 4);
        float4 x1l = *reinterpret_cast<const float4*>(p1);
        float4 x1h = *reinterpret_cast<const float4*>(p1 + 4);
        a0l.x += w0 * x0l.x; a0l.y += w0 * x0l.y; a0l.z += w0 * x0l.z; a0l.w += w0 * x0l.w;
        a0h.x += w0 * x0h.x; a0h.y += w0 * x0h.y; a0h.z += w0 * x0h.z; a0h.w += w0 * x0h.w;
        a1l.x += w1 * x1l.x; a1l.y += w1 * x1l.y; a1l.z += w1 * x1l.z; a1l.w += w1 * x1l.w;
        a1h.x += w1 * x1h.x; a1h.y += w1 * x1h.y; a1h.z += w1 * x1h.z; a1h.w += w1 * x1h.w;
    }
    if (idx < end) {
        int s0 = g_csr_src[idx];
        float w0 = g_csr_w[idx];
        const float* p0 = Xg + (size_t)s0 * xs + fl * 8;
        float4 x0l = *reinterpret_cast<const float4*>(p0);
        float4 x0h = *reinterpret_cast<const float4*>(p0 + 4);
        a0l.x += w0 * x0l.x; a0l.y += w0 * x0l.y; a0l.z += w0 * x0l.z; a0l.w += w0 * x0l.w;
        a0h.x += w0 * x0h.x; a0h.y += w0 * x0h.y; a0h.z += w0 * x0h.z; a0h.w += w0 * x0h.w;
    }
    rl.x = a0l.x + a1l.x; rl.y = a0l.y + a1l.y; rl.z = a0l.z + a1l.z; rl.w = a0l.w + a1l.w;
    rh.x = a0h.x + a1h.x; rh.y = a0h.y + a1h.y; rh.z = a0h.z + a1h.z; rh.w = a0h.w + a1h.w;
}

__device__ __forceinline__ void shfl_red8(float4& l, float4& h, int off) {
    l.x += __shfl_down_sync(0xffffffffu, l.x, off);
    l.y += __shfl_down_sync(0xffffffffu, l.y, off);
    l.z += __shfl_down_sync(0xffffffffu, l.z, off);
    l.w += __shfl_down_sync(0xffffffffu, l.w, off);
    h.x += __shfl_down_sync(0xffffffffu, h.x, off);
    h.y += __shfl_down_sync(0xffffffffu, h.y, off);
    h.z += __shfl_down_sync(0xffffffffu, h.z, off);
    h.w += __shfl_down_sync(0xffffffffu, h.w, off);
}

// prop A: S = Z1 + 2 * (L_hat @ Z2)   (Z sections strided)
template <int F>
__global__ void k_propA(const float* __restrict__ Xg, int xs,
                        const float* __restrict__ Z1n, int zs,
                        float* __restrict__ S) {
    constexpr int LPN = PCfg<F>::LPN;
    int warp = (blockIdx.x * blockDim.x + threadIdx.x) >> 5;
    if (warp >= NN) return;
    int lane = threadIdx.x & 31;
    int sub = lane / LPN, fl = lane % LPN;
    int beg = g_rowptr[warp], end = g_rowptr[warp + 1];

    float4 al, ah;
    prop_gather8<F>(Xg, xs, beg, end, sub, fl, al, ah);
#pragma unroll
    for (int off = 16; off >= LPN; off >>= 1) shfl_red8(al, ah, off);

    if (sub == 0) {
        const float* zp = Z1n + (size_t)warp * zs + fl * 8;
        float4 zl = *reinterpret_cast<const float4*>(zp);
        float4 zh = *reinterpret_cast<const float4*>(zp + 4);
        float4 ol, oh;
        ol.x = zl.x + 2.f * al.x; ol.y = zl.y + 2.f * al.y;
        ol.z = zl.z + 2.f * al.z; ol.w = zl.w + 2.f * al.w;
        oh.x = zh.x + 2.f * ah.x; oh.y = zh.y + 2.f * ah.y;
        oh.z = zh.z + 2.f * ah.z; oh.w = zh.w + 2.f * ah.w;
        float* sp = S + (size_t)warp * F + fl * 8;
        *reinterpret_cast<float4*>(sp)     = ol;
        *reinterpret_cast<float4*>(sp + 4) = oh;
    }
}

// prop B: H = lrelu( (Z0 + L_hat @ S) * scale + shift )
template <int F>
__global__ void k_propB(const float* __restrict__ Xg, int xs,
                        const float* __restrict__ Z0n, int zs,
                        const float* __restrict__ scale, const float* __restrict__ shift,
                        float* __restrict__ H) {
    constexpr int LPN = PCfg<F>::LPN;
    int warp = (blockIdx.x * blockDim.x + threadIdx.x) >> 5;
    if (warp >= NN) return;
    int lane = threadIdx.x & 31;
    int sub = lane / LPN, fl = lane % LPN;
    int beg = g_rowptr[warp], end = g_rowptr[warp + 1];

    float4 al, ah;
    prop_gather8<F>(Xg, xs, beg, end, sub, fl, al, ah);
#pragma unroll
    for (int off = 16; off >= LPN; off >>= 1) shfl_red8(al, ah, off);

    if (sub == 0) {
        const float* zp = Z0n + (size_t)warp * zs + fl * 8;
        float4 zl = *reinterpret_cast<const float4*>(zp);
        float4 zh = *reinterpret_cast<const float4*>(zp + 4);
        float4 scl = *reinterpret_cast<const float4*>(scale + fl * 8);
        float4 sch = *reinterpret_cast<const float4*>(scale + fl * 8 + 4);
        float4 shl = *reinterpret_cast<const float4*>(shift + fl * 8);
        float4 shh = *reinterpret_cast<const float4*>(shift + fl * 8 + 4);
        float4 ol, oh;
        ol.x = (zl.x + al.x) * scl.x + shl.x;
        ol.y = (zl.y + al.y) * scl.y + shl.y;
        ol.z = (zl.z + al.z) * scl.z + shl.z;
        ol.w = (zl.w + al.w) * scl.w + shl.w;
        oh.x = (zh.x + ah.x) * sch.x + shh.x;
        oh.y = (zh.y + ah.y) * sch.y + shh.y;
        oh.z = (zh.z + ah.z) * sch.z + shh.z;
        oh.w = (zh.w + ah.w) * sch.w + shh.w;
        ol.x = (ol.x > 0.f) ? ol.x : SLOPE * ol.x;
        ol.y = (ol.y > 0.f) ? ol.y : SLOPE * ol.y;
        ol.z = (ol.z > 0.f) ? ol.z : SLOPE * ol.z;
        ol.w = (ol.w > 0.f) ? ol.w : SLOPE * ol.w;
        oh.x = (oh.x > 0.f) ? oh.x : SLOPE * oh.x;
        oh.y = (oh.y > 0.f) ? oh.y : SLOPE * oh.y;
        oh.z = (oh.z > 0.f) ? oh.z : SLOPE * oh.z;
        oh.w = (oh.w > 0.f) ? oh.w : SLOPE * oh.w;
        float* hp = H + (size_t)warp * F + fl * 8;
        *reinterpret_cast<float4*>(hp)     = ol;
        *reinterpret_cast<float4*>(hp + 4) = oh;
    }
}

// ---------------- per-graph mean pool + head --------------------------------
#define PNODES 1024
__global__ void k_pool(const float* __restrict__ H, const int* __restrict__ batch) {
    __shared__ float ssum[GG * 16];
    __shared__ int   scnt[GG];
    for (int i = threadIdx.x; i < GG * 16; i += 256) ssum[i] = 0.f;
    for (int i = threadIdx.x; i < GG; i += 256) scnt[i] = 0;
    __syncthreads();

    int f   = threadIdx.x & 15;
    int sub = threadIdx.x >> 4;
    int base = blockIdx.x * PNODES;
    for (int n = sub; n < PNODES; n += 16) {
        int node = base + n;
        if (node >= NN) break;
        int b = batch[node];
        atomicAdd(&ssum[b * 16 + f], H[node * 16 + f]);
        if (f == 0) atomicAdd(&scnt[b], 1);
    }
    __syncthreads();
    for (int i = threadIdx.x; i < GG * 16; i += 256) atomicAdd(&g_pooled[i], ssum[i]);
    for (int i = threadIdx.x; i < GG; i += 256) atomicAdd(&g_pcnt[i], scnt[i]);
}

__global__ void k_final(const float* __restrict__ lw, const float* __restrict__ lb,
                        float* __restrict__ out) {
    int t = threadIdx.x;
    if (t >= GG * 2) return;
    int g = t >> 1, c = t & 1;
    float inv = 1.f / fmaxf((float)g_pcnt[g], 1.f);
    float s = 0.f;
#pragma unroll
    for (int f = 0; f < 16; f++) s += g_pooled[g * 16 + f] * lw[c * 16 + f];
    out[t] = s * inv + lb[c];
}

// ---------------- launch ----------------------------------------------------
extern "C" void kernel_launch(void* const* d_in, const int* in_sizes, int n_in,
                              void* d_out, int out_size) {
    const float* x     = (const float*)d_in[0];
    const int*   ei    = (const int*)  d_in[1];
    const int*   batch = (const int*)  d_in[2];
    const float* W1 = (const float*)d_in[3];
    const float* b1 = (const float*)d_in[4];
    const float* g1 = (const float*)d_in[5];
    const float* be1= (const float*)d_in[6];
    const float* m1 = (const float*)d_in[7];
    const float* v1 = (const float*)d_in[8];
    const float* W2 = (const float*)d_in[9];
    const float* b2 = (const float*)d_in[10];
    const float* g2 = (const float*)d_in[11];
    const float* be2= (const float*)d_in[12];
    const float* m2 = (const float*)d_in[13];
    const float* v2 = (const float*)d_in[14];
    const float* W3 = (const float*)d_in[15];
    const float* b3 = (const float*)d_in[16];
    const float* g3 = (const float*)d_in[17];
    const float* be3= (const float*)d_in[18];
    const float* m3 = (const float*)d_in[19];
    const float* v3 = (const float*)d_in[20];
    const float* lw = (const float*)d_in[21];
    const float* lb = (const float*)d_in[22];
    float* out = (float*)d_out;

    float *ZC, *S, *H1, *H2, *H3, *Wc1, *Wc2, *Wc3;
    float *sc1, *sh1, *sc2, *sh2, *sc3, *sh3;
    cudaGetSymbolAddress((void**)&ZC, g_ZC);
    cudaGetSymbolAddress((void**)&S,  g_S);
    cudaGetSymbolAddress((void**)&H1, g_H1);
    cudaGetSymbolAddress((void**)&H2, g_H2);
    cudaGetSymbolAddress((void**)&H3, g_H3);
    cudaGetSymbolAddress((void**)&Wc1, g_Wc1);
    cudaGetSymbolAddress((void**)&Wc2, g_Wc2);
    cudaGetSymbolAddress((void**)&Wc3, g_Wc3);
    cudaGetSymbolAddress((void**)&sc1, g_sc1);
    cudaGetSymbolAddress((void**)&sh1, g_sh1);
    cudaGetSymbolAddress((void**)&sc2, g_sc2);
    cudaGetSymbolAddress((void**)&sh2, g_sh2);
    cudaGetSymbolAddress((void**)&sc3, g_sc3);
    cudaGetSymbolAddress((void**)&sh3, g_sh3);

    // dynamic smem: W resident + 2 x (16 x BR) X slabs
    const int smem1 = (128 * 192 + 2 * 16 * 64) * 4;    // 104 KB (BR=64)
    const int smem2 = (64 * 96 + 2 * 16 * 128) * 4;     //  40 KB (BR=128)
    const int smem3 = (32 * 48 + 2 * 16 * 256) * 4;     //  38 KB (BR=256)
    cudaFuncSetAttribute((const void*)k_gemm<128, 64, 32, 64>,
                         cudaFuncAttributeMaxDynamicSharedMemorySize, smem1);
    cudaFuncSetAttribute((const void*)k_gemm<64, 32, 16, 128>,
                         cudaFuncAttributeMaxDynamicSharedMemorySize, smem2);
    cudaFuncSetAttribute((const void*)k_gemm<32, 16, 8, 256>,
                         cudaFuncAttributeMaxDynamicSharedMemorySize, smem3);

    const int TB = 256;
    const int GEMM_GRID = 296;   // quasi-persistent: 2 blocks per SM
    // launches 1-3: prelude (CSR-independent)
    k_zero <<<(NN + TB - 1) / TB, TB>>>();
    k_count<<<(EE + TB - 1) / TB, TB>>>(ei);
    k_prep <<<(24576 + 6144 + 1536 + 112 + TB - 1) / TB, TB>>>(
        W1, W2, W3, b1, g1, be1, m1, v1, b2, g2, be2, m2, v2, b3, g3, be3, m3, v3);

    // launch 4: layer-1 GEMM (profiled by ncu)
    k_gemm<128, 64, 32, 64><<<GEMM_GRID, 256, smem1>>>(x, Wc1, ZC);

    // CSR build (dinv fused into scan1)
    k_scan1<<<NB_SCAN, 1024>>>();
    k_scan2<<<1, 128>>>(NB_SCAN);
    k_scan3<<<(NN + TB - 1) / TB, TB>>>(NB_SCAN);
    k_fill <<<(EE + TB - 1) / TB, TB>>>(ei);

    int prop_grid = (NN * 32 + TB - 1) / TB;   // one warp per node

    // --- layer 1 props (sections of ZC: stride 192, offsets 0/64/128) ---
    k_propA<64><<<prop_grid, TB>>>(ZC + 128, 192, ZC + 64, 192, S);
    k_propB<64><<<prop_grid, TB>>>(S, 64, ZC, 192, sc1, sh1, H1);

    // --- layer 2: 64 -> 32 ---
    k_gemm<64, 32, 16, 128><<<GEMM_GRID, 256, smem2>>>(H1, Wc2, ZC);
    k_propA<32><<<prop_grid, TB>>>(ZC + 64, 96, ZC + 32, 96, S);
    k_propB<32><<<prop_grid, TB>>>(S, 32, ZC, 96, sc2, sh2, H2);

    // --- layer 3: 32 -> 16 ---
    k_gemm<32, 16, 8, 256><<<GEMM_GRID, 256, smem3>>>(H2, Wc3, ZC);
    k_propA<16><<<prop_grid, TB>>>(ZC + 32, 48, ZC + 16, 48, S);
    k_propB<16><<<prop_grid, TB>>>(S, 16, ZC, 48, sc3, sh3, H3);

    // --- pool + linear head ---
    k_pool <<<(NN + PNODES - 1) / PNODES, 256>>>(H3, batch);
    k_final<<<1, 128>>>(lw, lb, out);
}

// round 16
// speedup vs baseline: 1.1275x; 1.1275x over previous
#include <cuda_runtime.h>

#define NN 100000
#define EE 640000
#define GG 64
#define BN_EPS 1e-5f
#define SLOPE 0.01f
#define NB_SCAN 98   // ceil(100000/1024)

// ---------------- scratch (static device buffers) ---------------------------
__device__ int   g_deg[NN];
__device__ float g_dinv[NN];
__device__ int   g_cnt[NN];
__device__ int   g_rowptr[NN + 1];
__device__ int   g_cursor[NN];
__device__ int   g_bsums[128];
__device__ int   g_boffs[130];
__device__ int   g_csr_src[EE];
__device__ float g_csr_w[EE];

__device__ __align__(16) float g_ZC[NN * 192];   // packed [Z0|Z1|Z2] per layer
__device__ __align__(16) float g_S [NN * 64];
__device__ __align__(16) float g_H1[NN * 64];
__device__ __align__(16) float g_H2[NN * 32];
__device__ __align__(16) float g_H3[NN * 16];

__device__ __align__(16) float g_Wc1[128 * 192];  // [f][ Wd | W1 | W2 ]
__device__ __align__(16) float g_Wc2[64 * 96];
__device__ __align__(16) float g_Wc3[32 * 48];
__device__ __align__(16) float g_sc1[64], g_sh1[64];
__device__ __align__(16) float g_sc2[32], g_sh2[32];
__device__ __align__(16) float g_sc3[16], g_sh3[16];

__device__ float g_pooled[GG * 16];
__device__ int   g_pcnt[GG];

// ---------------- f32x2 packed helpers -------------------------------------
__device__ __forceinline__ unsigned long long ffma2(unsigned long long a,
                                                    unsigned long long b,
                                                    unsigned long long c) {
    unsigned long long d;
    asm("fma.rn.f32x2 %0, %1, %2, %3;" : "=l"(d) : "l"(a), "l"(b), "l"(c));
    return d;
}
__device__ __forceinline__ unsigned long long dup2(float h) {
    unsigned long long r;
    unsigned hi = __float_as_uint(h);
    asm("mov.b64 %0, {%1, %1};" : "=l"(r) : "r"(hi));
    return r;
}
__device__ __forceinline__ void unpack2(unsigned long long v, float& lo, float& hi) {
    unsigned a, b;
    asm("mov.b64 {%0, %1}, %2;" : "=r"(a), "=r"(b) : "l"(v));
    lo = __uint_as_float(a);
    hi = __uint_as_float(b);
}

// ---------------- init ------------------------------------------------------
__global__ void k_zero() {
    int i = blockIdx.x * blockDim.x + threadIdx.x;
    if (i < NN) { g_deg[i] = 0; g_cnt[i] = 0; g_cursor[i] = 0; }
    if (i < GG * 16) g_pooled[i] = 0.f;
    if (i < GG) g_pcnt[i] = 0;
}

__global__ void k_count(const int* __restrict__ ei) {
    int e = blockIdx.x * blockDim.x + threadIdx.x;
    if (e >= EE) return;
    int s = ei[e], d = ei[EE + e];
    if (s != d) {
        atomicAdd(&g_deg[s], 1);
        atomicAdd(&g_cnt[d], 1);
    }
}

// ---------------- exclusive scan of g_cnt -> g_rowptr (+ dinv fused) -------
__global__ void k_scan1() {
    __shared__ int sm[1024];
    int t = threadIdx.x;
    int i = blockIdx.x * 1024 + t;
    int v = (i < NN) ? g_cnt[i] : 0;
    if (i < NN) {   // fused dinv (g_deg final after k_count)
        int dg = g_deg[i];
        g_dinv[i] = (dg > 0) ? rsqrtf((float)dg) : 0.f;
    }
    sm[t] = v;
    __syncthreads();
    for (int off = 1; off < 1024; off <<= 1) {
        int add = (t >= off) ? sm[t - off] : 0;
        __syncthreads();
        sm[t] += add;
        __syncthreads();
    }
    if (i < NN) g_rowptr[i] = sm[t] - v;
    if (t == 1023) g_bsums[blockIdx.x] = sm[1023];
}

__global__ void k_scan2(int nb) {
    __shared__ int sm[128];
    int t = threadIdx.x;
    int v = (t < nb) ? g_bsums[t] : 0;
    sm[t] = v;
    __syncthreads();
    for (int off = 1; off < 128; off <<= 1) {
        int add = (t >= off) ? sm[t - off] : 0;
        __syncthreads();
        sm[t] += add;
        __syncthreads();
    }
    if (t < nb) g_boffs[t] = sm[t] - v;
    if (t == nb - 1) g_boffs[nb] = sm[t];
}

__global__ void k_scan3(int nb) {
    int i = blockIdx.x * blockDim.x + threadIdx.x;
    if (i < NN) g_rowptr[i] += g_boffs[i >> 10];
    if (i == 0) g_rowptr[NN] = g_boffs[nb];
}

__global__ void k_fill(const int* __restrict__ ei) {
    int e = blockIdx.x * blockDim.x + threadIdx.x;
    if (e >= EE) return;
    int s = ei[e], d = ei[EE + e];
    if (s == d) return;
    float wv = -g_dinv[s] * g_dinv[d];
    int pos = g_rowptr[d] + atomicAdd(&g_cursor[d], 1);
    g_csr_src[pos] = s;
    g_csr_w[pos]   = wv;
}

// ---------------- prep: concatenated weights + BN affine fold ---------------
__global__ void k_prep(const float* __restrict__ W1, const float* __restrict__ W2,
                       const float* __restrict__ W3,
                       const float* __restrict__ b1, const float* __restrict__ gg1,
                       const float* __restrict__ be1, const float* __restrict__ m1,
                       const float* __restrict__ v1,
                       const float* __restrict__ b2, const float* __restrict__ gg2,
                       const float* __restrict__ be2, const float* __restrict__ m2,
                       const float* __restrict__ v2,
                       const float* __restrict__ b3, const float* __restrict__ gg3,
                       const float* __restrict__ be3, const float* __restrict__ m3,
                       const float* __restrict__ v3) {
    int i = blockIdx.x * blockDim.x + threadIdx.x;
    if (i < 24576) {                        // 128 x 192
        int f = i / 192, c = i % 192;
        int sec = c / 64, cc = c - sec * 64;
        int base = f * 64 + cc;
        float v = (sec == 0) ? (W1[base] - W1[16384 + base]) : W1[sec * 8192 + base];
        g_Wc1[i] = v;
    } else if (i < 24576 + 6144) {          // 64 x 96
        int j = i - 24576;
        int f = j / 96, c = j % 96;
        int sec = c / 32, cc = c - sec * 32;
        int base = f * 32 + cc;
        float v = (sec == 0) ? (W2[base] - W2[4096 + base]) : W2[sec * 2048 + base];
        g_Wc2[j] = v;
    } else if (i < 24576 + 6144 + 1536) {   // 32 x 48
        int j = i - 24576 - 6144;
        int f = j / 48, c = j % 48;
        int sec = c / 16, cc = c - sec * 16;
        int base = f * 16 + cc;
        float v = (sec == 0) ? (W3[base] - W3[1024 + base]) : W3[sec * 512 + base];
        g_Wc3[j] = v;
    } else if (i < 24576 + 6144 + 1536 + 64) {
        int o = i - (24576 + 6144 + 1536);
        float s = gg1[o] * rsqrtf(v1[o] + BN_EPS);
        g_sc1[o] = s;
        g_sh1[o] = be1[o] + (b1[o] - m1[o]) * s;
    } else if (i < 24576 + 6144 + 1536 + 64 + 32) {
        int o = i - (24576 + 6144 + 1536 + 64);
        float s = gg2[o] * rsqrtf(v2[o] + BN_EPS);
        g_sc2[o] = s;
        g_sh2[o] = be2[o] + (b2[o] - m2[o]) * s;
    } else if (i < 24576 + 6144 + 1536 + 64 + 32 + 16) {
        int o = i - (24576 + 6144 + 1536 + 64 + 32);
        float s = gg3[o] * rsqrtf(v3[o] + BN_EPS);
        g_sc3[o] = s;
        g_sh3[o] = be3[o] + (b3[o] - m3[o]) * s;
    }
}

// ---------------- persistent-W pipelined GEMM (column-split capable) --------
// ZC[N x 3Fout] = X[N x Fin] @ Wc.  Each block holds NC of the N3 columns of
// W resident in smem (col0 = blockIdx.y * NC); blocks stride over BR-row
// chunks.  Double-buffered transposed X slabs, one barrier per slab, strided
// column map, software-pipelined kk loop.  Layer 1 uses NC=96 (49KB W slice)
// -> 57KB smem/block -> 3 blocks/SM (24 warps).
// Pair p covers rows 2p,2p+1 -> X pair load offset is p*2 floats (R15 bug:
// p*4 read OOB for PAIRS=4).
template <int Fin, int Fout, int CT, int BR, int NC, int MINB>
__global__ void __launch_bounds__(256, MINB)
k_gemm(const float* __restrict__ X, const float* __restrict__ Wc,
       float* __restrict__ ZC) {
    constexpr int N3     = 3 * Fout;
    constexpr int TC     = NC / CT;           // 6
    constexpr int RT     = 256 / CT;
    constexpr int TR     = BR / RT;
    constexpr int PAIRS  = TR / 2;
    constexpr int KS     = Fin / 16;          // k slabs (even)
    constexpr int PER    = (BR * 4) / 256;    // staged float4s per thread
    constexpr int NCHK   = (NN + BR - 1) / BR;

    extern __shared__ float smem[];
    float* Ws = smem;                         // [Fin][NC]
    float* Xs = smem + Fin * NC;              // [2][16][BR]

    int tid = threadIdx.x;
    int ct = tid % CT, rt = tid / CT;
    int tr0 = rt * TR;
    int sr  = tid % BR;                       // staging row
    int kq0 = tid / BR;                       // staging k-quad base
    int col0 = blockIdx.y * NC;

    // load this block's W column slice once
    for (int i = tid; i < Fin * NC / 4; i += 256) {
        int f = i / (NC / 4);
        int cq = i % (NC / 4);
        *reinterpret_cast<float4*>(Ws + f * NC + cq * 4) =
            *reinterpret_cast<const float4*>(Wc + f * N3 + col0 + cq * 4);
    }
    __syncthreads();

    for (int chunk = blockIdx.x; chunk < NCHK; chunk += gridDim.x) {
        int row0 = chunk * BR;
        const float* xbase = X + (size_t)min(row0 + sr, NN - 1) * Fin;

        unsigned long long acc[PAIRS][TC];
#pragma unroll
        for (int p = 0; p < PAIRS; p++)
#pragma unroll
            for (int c = 0; c < TC; c++) acc[p][c] = 0ull;

        float4 xreg[PER];
#pragma unroll
        for (int q = 0; q < PER; q++)
            xreg[q] = *reinterpret_cast<const float4*>(
                xbase + (kq0 + q * (256 / BR)) * 4);

#pragma unroll
        for (int ki = 0; ki < KS; ki++) {
            float* Xb = Xs + (ki & 1) * (16 * BR);
#pragma unroll
            for (int q = 0; q < PER; q++) {
                int kq = kq0 + q * (256 / BR);
                Xb[(kq * 4 + 0) * BR + sr] = xreg[q].x;
                Xb[(kq * 4 + 1) * BR + sr] = xreg[q].y;
                Xb[(kq * 4 + 2) * BR + sr] = xreg[q].z;
                Xb[(kq * 4 + 3) * BR + sr] = xreg[q].w;
            }
            if (ki + 1 < KS) {   // prefetch next slab (hidden under compute)
#pragma unroll
                for (int q = 0; q < PER; q++)
                    xreg[q] = *reinterpret_cast<const float4*>(
                        xbase + (ki + 1) * 16 + (kq0 + q * (256 / BR)) * 4);
            }
            __syncthreads();     // single barrier per slab

            const float* Wk = Ws + ki * 16 * NC + ct;

            // ---- software-pipelined kk loop (double reg buffer) ----
            float wv[2][TC];
            unsigned long long xp[2][PAIRS];
#pragma unroll
            for (int c = 0; c < TC; c++) wv[0][c] = Wk[c * CT];
            {
                const float* xrow = Xb + tr0;
#pragma unroll
                for (int p = 0; p < PAIRS; p += 2) {
                    ulonglong2 a = *reinterpret_cast<const ulonglong2*>(xrow + p * 2);
                    xp[0][p] = a.x;
                    if (p + 1 < PAIRS) xp[0][p + 1] = a.y;
                }
            }
#pragma unroll
            for (int kk = 0; kk < 16; kk++) {
                int cur = kk & 1, nxt = cur ^ 1;
                if (kk + 1 < 16) {
#pragma unroll
                    for (int c = 0; c < TC; c++)
                        wv[nxt][c] = Wk[(kk + 1) * NC + c * CT];
                    const float* xrow = Xb + (kk + 1) * BR + tr0;
#pragma unroll
                    for (int p = 0; p < PAIRS; p += 2) {
                        ulonglong2 a = *reinterpret_cast<const ulonglong2*>(xrow + p * 2);
                        xp[nxt][p] = a.x;
                        if (p + 1 < PAIRS) xp[nxt][p + 1] = a.y;
                    }
                }
#pragma unroll
                for (int c = 0; c < TC; c++) {
                    unsigned long long wd = dup2(wv[cur][c]);
#pragma unroll
                    for (int p = 0; p < PAIRS; p++)
                        acc[p][c] = ffma2(xp[cur][p], wd, acc[p][c]);
                }
            }
        }

#pragma unroll
        for (int p = 0; p < PAIRS; p++) {
            int row = row0 + tr0 + 2 * p;
            float lo[TC], hi[TC];
#pragma unroll
            for (int c = 0; c < TC; c++) unpack2(acc[p][c], lo[c], hi[c]);
            if (row < NN) {
#pragma unroll
                for (int c = 0; c < TC; c++)
                    ZC[(size_t)row * N3 + col0 + c * CT + ct] = lo[c];
            }
            if (row + 1 < NN) {
#pragma unroll
                for (int c = 0; c < TC; c++)
                    ZC[(size_t)(row + 1) * N3 + col0 + c * CT + ct] = hi[c];
            }
        }
    }
}

// ---------------- props: one warp per node, unroll-2 edge loop (R13) --------
// prop A: S = Z1 + 2 * (L_hat @ Z2)   (Z sections strided)
template <int F>
__global__ void k_propA(const float* __restrict__ Xg, int xs,
                        const float* __restrict__ Z1n, int zs,
                        float* __restrict__ S) {
    constexpr int LPN = F / 4;
    constexpr int EPW = 32 / LPN;
    int warp = (blockIdx.x * blockDim.x + threadIdx.x) >> 5;
    if (warp >= NN) return;
    int lane = threadIdx.x & 31;
    int sub = lane / LPN, fl = lane % LPN;
    int beg = g_rowptr[warp], end = g_rowptr[warp + 1];

    float4 a0 = make_float4(0.f, 0.f, 0.f, 0.f);
    float4 a1 = make_float4(0.f, 0.f, 0.f, 0.f);
    int idx = beg + sub;
    for (; idx + EPW < end; idx += 2 * EPW) {
        int s0 = g_csr_src[idx],       s1 = g_csr_src[idx + EPW];
        float w0 = g_csr_w[idx],       w1 = g_csr_w[idx + EPW];
        float4 x0 = *reinterpret_cast<const float4*>(Xg + (size_t)s0 * xs + fl * 4);
        float4 x1 = *reinterpret_cast<const float4*>(Xg + (size_t)s1 * xs + fl * 4);
        a0.x += w0 * x0.x; a0.y += w0 * x0.y; a0.z += w0 * x0.z; a0.w += w0 * x0.w;
        a1.x += w1 * x1.x; a1.y += w1 * x1.y; a1.z += w1 * x1.z; a1.w += w1 * x1.w;
    }
    if (idx < end) {
        int s0 = g_csr_src[idx];
        float w0 = g_csr_w[idx];
        float4 x0 = *reinterpret_cast<const float4*>(Xg + (size_t)s0 * xs + fl * 4);
        a0.x += w0 * x0.x; a0.y += w0 * x0.y; a0.z += w0 * x0.z; a0.w += w0 * x0.w;
    }
    float4 acc;
    acc.x = a0.x + a1.x; acc.y = a0.y + a1.y;
    acc.z = a0.z + a1.z; acc.w = a0.w + a1.w;
#pragma unroll
    for (int off = 16; off >= LPN; off >>= 1) {
        acc.x += __shfl_down_sync(0xffffffffu, acc.x, off);
        acc.y += __shfl_down_sync(0xffffffffu, acc.y, off);
        acc.z += __shfl_down_sync(0xffffffffu, acc.z, off);
        acc.w += __shfl_down_sync(0xffffffffu, acc.w, off);
    }
    if (sub == 0) {
        float4 z = *reinterpret_cast<const float4*>(Z1n + (size_t)warp * zs + fl * 4);
        float4 o;
        o.x = z.x + 2.f * acc.x; o.y = z.y + 2.f * acc.y;
        o.z = z.z + 2.f * acc.z; o.w = z.w + 2.f * acc.w;
        *reinterpret_cast<float4*>(S + (size_t)warp * F + fl * 4) = o;
    }
}

// prop B: H = lrelu( (Z0 + L_hat @ S) * scale + shift )
template <int F>
__global__ void k_propB(const float* __restrict__ Xg, int xs,
                        const float* __restrict__ Z0n, int zs,
                        const float* __restrict__ scale, const float* __restrict__ shift,
                        float* __restrict__ H) {
    constexpr int LPN = F / 4;
    constexpr int EPW = 32 / LPN;
    int warp = (blockIdx.x * blockDim.x + threadIdx.x) >> 5;
    if (warp >= NN) return;
    int lane = threadIdx.x & 31;
    int sub = lane / LPN, fl = lane % LPN;
    int beg = g_rowptr[warp], end = g_rowptr[warp + 1];

    float4 a0 = make_float4(0.f, 0.f, 0.f, 0.f);
    float4 a1 = make_float4(0.f, 0.f, 0.f, 0.f);
    int idx = beg + sub;
    for (; idx + EPW < end; idx += 2 * EPW) {
        int s0 = g_csr_src[idx],       s1 = g_csr_src[idx + EPW];
        float w0 = g_csr_w[idx],       w1 = g_csr_w[idx + EPW];
        float4 x0 = *reinterpret_cast<const float4*>(Xg + (size_t)s0 * xs + fl * 4);
        float4 x1 = *reinterpret_cast<const float4*>(Xg + (size_t)s1 * xs + fl * 4);
        a0.x += w0 * x0.x; a0.y += w0 * x0.y; a0.z += w0 * x0.z; a0.w += w0 * x0.w;
        a1.x += w1 * x1.x; a1.y += w1 * x1.y; a1.z += w1 * x1.z; a1.w += w1 * x1.w;
    }
    if (idx < end) {
        int s0 = g_csr_src[idx];
        float w0 = g_csr_w[idx];
        float4 x0 = *reinterpret_cast<const float4*>(Xg + (size_t)s0 * xs + fl * 4);
        a0.x += w0 * x0.x; a0.y += w0 * x0.y; a0.z += w0 * x0.z; a0.w += w0 * x0.w;
    }
    float4 acc;
    acc.x = a0.x + a1.x; acc.y = a0.y + a1.y;
    acc.z = a0.z + a1.z; acc.w = a0.w + a1.w;
#pragma unroll
    for (int off = 16; off >= LPN; off >>= 1) {
        acc.x += __shfl_down_sync(0xffffffffu, acc.x, off);
        acc.y += __shfl_down_sync(0xffffffffu, acc.y, off);
        acc.z += __shfl_down_sync(0xffffffffu, acc.z, off);
        acc.w += __shfl_down_sync(0xffffffffu, acc.w, off);
    }
    if (sub == 0) {
        float4 z  = *reinterpret_cast<const float4*>(Z0n + (size_t)warp * zs + fl * 4);
        float4 sc = *reinterpret_cast<const float4*>(scale + fl * 4);
        float4 sh = *reinterpret_cast<const float4*>(shift + fl * 4);
        float4 o;
        o.x = (z.x + acc.x) * sc.x + sh.x;
        o.y = (z.y + acc.y) * sc.y + sh.y;
        o.z = (z.z + acc.z) * sc.z + sh.z;
        o.w = (z.w + acc.w) * sc.w + sh.w;
        o.x = (o.x > 0.f) ? o.x : SLOPE * o.x;
        o.y = (o.y > 0.f) ? o.y : SLOPE * o.y;
        o.z = (o.z > 0.f) ? o.z : SLOPE * o.z;
        o.w = (o.w > 0.f) ? o.w : SLOPE * o.w;
        *reinterpret_cast<float4*>(H + (size_t)warp * F + fl * 4) = o;
    }
}

// ---------------- per-graph mean pool + head --------------------------------
#define PNODES 1024
__global__ void k_pool(const float* __restrict__ H, const int* __restrict__ batch) {
    __shared__ float ssum[GG * 16];
    __shared__ int   scnt[GG];
    for (int i = threadIdx.x; i < GG * 16; i += 256) ssum[i] = 0.f;
    for (int i = threadIdx.x; i < GG; i += 256) scnt[i] = 0;
    __syncthreads();

    int f   = threadIdx.x & 15;
    int sub = threadIdx.x >> 4;
    int base = blockIdx.x * PNODES;
    for (int n = sub; n < PNODES; n += 16) {
        int node = base + n;
        if (node >= NN) break;
        int b = batch[node];
        atomicAdd(&ssum[b * 16 + f], H[node * 16 + f]);
        if (f == 0) atomicAdd(&scnt[b], 1);
    }
    __syncthreads();
    for (int i = threadIdx.x; i < GG * 16; i += 256) atomicAdd(&g_pooled[i], ssum[i]);
    for (int i = threadIdx.x; i < GG; i += 256) atomicAdd(&g_pcnt[i], scnt[i]);
}

__global__ void k_final(const float* __restrict__ lw, const float* __restrict__ lb,
                        float* __restrict__ out) {
    int t = threadIdx.x;
    if (t >= GG * 2) return;
    int g = t >> 1, c = t & 1;
    float inv = 1.f / fmaxf((float)g_pcnt[g], 1.f);
    float s = 0.f;
#pragma unroll
    for (int f = 0; f < 16; f++) s += g_pooled[g * 16 + f] * lw[c * 16 + f];
    out[t] = s * inv + lb[c];
}

// ---------------- launch ----------------------------------------------------
extern "C" void kernel_launch(void* const* d_in, const int* in_sizes, int n_in,
                              void* d_out, int out_size) {
    const float* x     = (const float*)d_in[0];
    const int*   ei    = (const int*)  d_in[1];
    const int*   batch = (const int*)  d_in[2];
    const float* W1 = (const float*)d_in[3];
    const float* b1 = (const float*)d_in[4];
    const float* g1 = (const float*)d_in[5];
    const float* be1= (const float*)d_in[6];
    const float* m1 = (const float*)d_in[7];
    const float* v1 = (const float*)d_in[8];
    const float* W2 = (const float*)d_in[9];
    const float* b2 = (const float*)d_in[10];
    const float* g2 = (const float*)d_in[11];
    const float* be2= (const float*)d_in[12];
    const float* m2 = (const float*)d_in[13];
    const float* v2 = (const float*)d_in[14];
    const float* W3 = (const float*)d_in[15];
    const float* b3 = (const float*)d_in[16];
    const float* g3 = (const float*)d_in[17];
    const float* be3= (const float*)d_in[18];
    const float* m3 = (const float*)d_in[19];
    const float* v3 = (const float*)d_in[20];
    const float* lw = (const float*)d_in[21];
    const float* lb = (const float*)d_in[22];
    float* out = (float*)d_out;

    float *ZC, *S, *H1, *H2, *H3, *Wc1, *Wc2, *Wc3;
    float *sc1, *sh1, *sc2, *sh2, *sc3, *sh3;
    cudaGetSymbolAddress((void**)&ZC, g_ZC);
    cudaGetSymbolAddress((void**)&S,  g_S);
    cudaGetSymbolAddress((void**)&H1, g_H1);
    cudaGetSymbolAddress((void**)&H2, g_H2);
    cudaGetSymbolAddress((void**)&H3, g_H3);
    cudaGetSymbolAddress((void**)&Wc1, g_Wc1);
    cudaGetSymbolAddress((void**)&Wc2, g_Wc2);
    cudaGetSymbolAddress((void**)&Wc3, g_Wc3);
    cudaGetSymbolAddress((void**)&sc1, g_sc1);
    cudaGetSymbolAddress((void**)&sh1, g_sh1);
    cudaGetSymbolAddress((void**)&sc2, g_sc2);
    cudaGetSymbolAddress((void**)&sh2, g_sh2);
    cudaGetSymbolAddress((void**)&sc3, g_sc3);
    cudaGetSymbolAddress((void**)&sh3, g_sh3);

    // dynamic smem: W column slice + 2 x (16 x BR) X slabs
    const int smem1 = (128 * 96 + 2 * 16 * 64) * 4;     //  57344 (NC=96, 3/SM)
    const int smem2 = (64 * 96 + 2 * 16 * 128) * 4;     //  40960
    const int smem3 = (32 * 48 + 2 * 16 * 256) * 4;     //  38912
    cudaFuncSetAttribute((const void*)k_gemm<128, 64, 16, 64, 96, 3>,
                         cudaFuncAttributeMaxDynamicSharedMemorySize, smem1);
    cudaFuncSetAttribute((const void*)k_gemm<64, 32, 16, 128, 96, 2>,
                         cudaFuncAttributeMaxDynamicSharedMemorySize, smem2);
    cudaFuncSetAttribute((const void*)k_gemm<32, 16, 8, 256, 48, 2>,
                         cudaFuncAttributeMaxDynamicSharedMemorySize, smem3);

    const int TB = 256;
    // launches 1-3: prelude (CSR-independent)
    k_zero <<<(NN + TB - 1) / TB, TB>>>();
    k_count<<<(EE + TB - 1) / TB, TB>>>(ei);
    k_prep <<<(24576 + 6144 + 1536 + 112 + TB - 1) / TB, TB>>>(
        W1, W2, W3, b1, g1, be1, m1, v1, b2, g2, be2, m2, v2, b3, g3, be3, m3, v3);

    // launch 4: layer-1 GEMM, column-split (grid.y = 2, 3 blocks/SM)
    k_gemm<128, 64, 16, 64, 96, 3><<<dim3(444, 2), 256, smem1>>>(x, Wc1, ZC);

    // CSR build (dinv fused into scan1)
    k_scan1<<<NB_SCAN, 1024>>>();
    k_scan2<<<1, 128>>>(NB_SCAN);
    k_scan3<<<(NN + TB - 1) / TB, TB>>>(NB_SCAN);
    k_fill <<<(EE + TB - 1) / TB, TB>>>(ei);

    int prop_grid = (NN * 32 + TB - 1) / TB;   // one warp per node

    // --- layer 1 props (sections of ZC: stride 192, offsets 0/64/128) ---
    k_propA<64><<<prop_grid, TB>>>(ZC + 128, 192, ZC + 64, 192, S);
    k_propB<64><<<prop_grid, TB>>>(S, 64, ZC, 192, sc1, sh1, H1);

    // --- layer 2: 64 -> 32 ---
    k_gemm<64, 32, 16, 128, 96, 2><<<dim3(296, 1), 256, smem2>>>(H1, Wc2, ZC);
    k_propA<32><<<prop_grid, TB>>>(ZC + 64, 96, ZC + 32, 96, S);
    k_propB<32><<<prop_grid, TB>>>(S, 32, ZC, 96, sc2, sh2, H2);

    // --- layer 3: 32 -> 16 ---
    k_gemm<32, 16, 8, 256, 48, 2><<<dim3(296, 1), 256, smem3>>>(H2, Wc3, ZC);
    k_propA<16><<<prop_grid, TB>>>(ZC + 32, 48, ZC + 16, 48, S);
    k_propB<16><<<prop_grid, TB>>>(S, 16, ZC, 48, sc3, sh3, H3);

    // --- pool + linear head ---
    k_pool <<<(NN + PNODES - 1) / PNODES, 256>>>(H3, batch);
    k_final<<<1, 128>>>(lw, lb, out);
}